// round 12
// baseline (speedup 1.0000x reference)
#include <cuda_runtime.h>
#include <cuda_bf16.h>
#include <math.h>
#include <stdint.h>

#define DIM 1024
constexpr int B_ = 8, S_ = 512, L_ = 4;
constexpr int M_ = B_ * S_;
constexpr int V_ = 32000;
constexpr int STEPS = 8;
constexpr float LR = 0.1f;
constexpr int MD = M_ * DIM, LMD = L_ * MD;
constexpr int NROWS = B_ * (S_ - 1);
constexpr int NSP = V_ / 128;     // 250
constexpr int NPCB = 256, NCEB = 16;
constexpr float SINV = 1.f / 4194304.f;   // 2^-22

__device__ float g_x[MD];
__device__ float g_states[LMD];
__device__ __nv_bfloat16 g_sh[LMD], g_eh[LMD];
__device__ int8_t g_s1[LMD], g_s2[LMD], g_e1[LMD], g_e2[LMD];
__device__ __nv_bfloat16 g_Wh[L_*DIM*DIM], g_Wth[L_*DIM*DIM];
__device__ int8_t g_Wl8[L_*DIM*DIM], g_Wh8[L_*DIM*DIM];
__device__ int8_t g_Wtl8[L_*DIM*DIM], g_Wth8[L_*DIM*DIM];
__device__ __nv_bfloat16 g_oWh[V_*DIM];
__device__ float g_pm[4096*NSP], g_ps[4096*NSP], g_pt[4096*NSP];
__device__ double g_pc_part[NPCB], g_ce_part[NCEB];

// ---- helpers ----
__device__ __forceinline__ uint32_t smem_u32(const void* p){
    uint32_t a; asm("{ .reg .u64 t; cvta.to.shared.u64 t, %1; cvt.u32.u64 %0, t; }":"=r"(a):"l"(p)); return a;
}
__device__ __forceinline__ int q8(float v){
    int q = __float2int_rn(v); return q > 127 ? 127 : (q < -127 ? -127 : q);
}
#define CP16(dst, src) \
    asm volatile("cp.async.cg.shared.global [%0], [%1], 16;" \
        :: "r"(dst), "l"(__cvta_generic_to_global(src)) : "memory")
#define CP_COMMIT() asm volatile("cp.async.commit_group;" ::: "memory")
#define CP_WAIT1()  asm volatile("cp.async.wait_group 1;" ::: "memory")
#define CP_WAIT0()  asm volatile("cp.async.wait_group 0;" ::: "memory")
#define LDSM4(r0,r1,r2,r3,addr) \
    asm volatile("ldmatrix.sync.aligned.m8n8.x4.shared.b16 {%0,%1,%2,%3}, [%4];" \
        : "=r"(r0),"=r"(r1),"=r"(r2),"=r"(r3) : "r"(addr))
#define MMA(d, a, b) \
    asm volatile("mma.sync.aligned.m16n8k16.row.col.f32.bf16.bf16.f32 " \
        "{%0,%1,%2,%3},{%4,%5,%6,%7},{%8,%9},{%0,%1,%2,%3};" \
        : "+f"((d)[0]),"+f"((d)[1]),"+f"((d)[2]),"+f"((d)[3]) \
        : "r"((a)[0]),"r"((a)[1]),"r"((a)[2]),"r"((a)[3]),"r"((b)[0]),"r"((b)[1]))
#define MMAI(d, a, b) \
    asm volatile("mma.sync.aligned.m16n8k32.row.col.s32.s8.s8.s32 " \
        "{%0,%1,%2,%3},{%4,%5,%6,%7},{%8,%9},{%0,%1,%2,%3};" \
        : "+r"((d)[0]),"+r"((d)[1]),"+r"((d)[2]),"+r"((d)[3]) \
        : "r"((a)[0]),"r"((a)[1]),"r"((a)[2]),"r"((a)[3]),"r"((b)[0]),"r"((b)[1]))

// ---- prep kernels ----
__global__ void gather_kernel(const int* __restrict__ ids, const float* __restrict__ emb){
    int row = blockIdx.x, id = ids[row];
    reinterpret_cast<float4*>(g_x + (size_t)row*DIM)[threadIdx.x] =
        reinterpret_cast<const float4*>(emb + (size_t)id*DIM)[threadIdx.x];
}
__global__ void split_states_kernel(const float* __restrict__ si){
    int i = blockIdx.x*blockDim.x + threadIdx.x;   // over LMD/4
    float4 v = reinterpret_cast<const float4*>(si)[i];
    reinterpret_cast<float4*>(g_states)[i] = v;
    float e[4] = {v.x, v.y, v.z, v.w};
    __nv_bfloat162 hp[2];
    uint32_t p1 = 0, p2 = 0;
    #pragma unroll
    for (int q = 0; q < 4; q++){
        __nv_bfloat16 h = __float2bfloat16(e[q]);
        if (q < 2){ if (q == 0) hp[0].x = h; else hp[0].y = h; }
        else      { if (q == 2) hp[1].x = h; else hp[1].y = h; }
        p1 |= ((uint32_t)(q8(e[q]*16.f) & 0xFF)) << (q*8);
        p2 |= ((uint32_t)(q8((e[q] - __bfloat162float(h))*8192.f) & 0xFF)) << (q*8);
    }
    reinterpret_cast<uint2*>(g_sh)[i] = *reinterpret_cast<uint2*>(hp);
    reinterpret_cast<uint32_t*>(g_s1)[i] = p1;
    reinterpret_cast<uint32_t*>(g_s2)[i] = p2;
}
__global__ void split_w_kernel(const float* __restrict__ W){
    __shared__ float tile[32][33];
    int l = blockIdx.z, i0 = blockIdx.y*32, j0 = blockIdx.x*32;
    int tx = threadIdx.x, ty = threadIdx.y;
    const float* Wb = W + (size_t)l*DIM*DIM;
    #pragma unroll
    for (int r = 0; r < 4; r++){
        int i = i0 + ty + r*8;
        float w = Wb[(size_t)i*DIM + j0 + tx];
        __nv_bfloat16 h = __float2bfloat16(w);
        float hf = __bfloat162float(h);
        size_t o = (size_t)l*DIM*DIM + (size_t)i*DIM + j0 + tx;
        g_Wh[o] = h;
        g_Wl8[o] = (int8_t)q8((w - hf)*262144.f);
        g_Wh8[o] = (int8_t)q8(hf*512.f);
        tile[ty + r*8][tx] = w;
    }
    __syncthreads();
    #pragma unroll
    for (int r = 0; r < 4; r++){
        int jr = ty + r*8;
        float w = tile[tx][jr];
        __nv_bfloat16 h = __float2bfloat16(w);
        float hf = __bfloat162float(h);
        size_t o = (size_t)l*DIM*DIM + (size_t)(j0+jr)*DIM + i0 + tx;
        g_Wth[o] = h;
        g_Wtl8[o] = (int8_t)q8((w - hf)*262144.f);
        g_Wth8[o] = (int8_t)q8(hf*512.f);
    }
}
__global__ void split_ow_kernel(const float* __restrict__ oW){
    int i = blockIdx.x*blockDim.x + threadIdx.x;   // over V*DIM/4
    float4 v = reinterpret_cast<const float4*>(oW)[i];
    __nv_bfloat162 hp[2];
    hp[0].x = __float2bfloat16(v.x); hp[0].y = __float2bfloat16(v.y);
    hp[1].x = __float2bfloat16(v.z); hp[1].y = __float2bfloat16(v.w);
    reinterpret_cast<uint2*>(g_oWh)[i] = *reinterpret_cast<uint2*>(hp);
}

// ---- step GEMM: 128x256 block, 8 warps of 64x64, unified 64-kt loop ----
// kts 0-15:  int8  a1(16A)        x wl(2^18(W-Whb))
// kts 16-31: int8  a2(2^13(A-Ah)) x wh(2^9 Whb)   -> same s32 acc, x 2^-22
// kts 32-63: bf16  Ahb x Whb  -> f32, accumulated IN PLACE on the converted acc
// One uint32 accumulator array serves both phases (no register doubling).
// stage (30720B): A@0 (128 rows x 64B, stride 80), B@10240 (256 rows x 64B, stride 80)
template<int MODE>
__global__ __launch_bounds__(256,1)
void mm_step(const float* __restrict__ bst){
    extern __shared__ char smem[];
    const uint32_t sb = smem_u32(smem);
    const int tid = threadIdx.x;
    const int k = blockIdx.z;
    const int m0 = blockIdx.y*128, n0 = blockIdx.x*256;
    const size_t abase = (size_t)k*MD + (size_t)m0*DIM;
    const size_t bbase = (size_t)k*DIM*DIM + (size_t)n0*DIM;
    const __nv_bfloat16* Ah = (MODE==0?g_sh:g_eh) + abase;
    const int8_t* A1 = (MODE==0?g_s1:g_e1) + abase;
    const int8_t* A2 = (MODE==0?g_s2:g_e2) + abase;
    const __nv_bfloat16* Bh = (MODE==0?g_Wh:g_Wth) + bbase;
    const int8_t* Bl8 = (MODE==0?g_Wl8:g_Wtl8) + bbase;
    const int8_t* Bh8 = (MODE==0?g_Wh8:g_Wth8) + bbase;

    auto issue = [&](int kt){
        const uint32_t st = sb + (uint32_t)(kt%3)*30720u;
        if (kt < 32){
            const int8_t* As = (kt < 16) ? A1 : A2;
            const int8_t* Bs = (kt < 16) ? Bl8 : Bh8;
            const int k0 = (kt & 15)*64;
            #pragma unroll
            for (int it = 0; it < 2; it++){
                int c = it*256 + tid, row = c>>2, cc = c&3;
                CP16(st + row*80 + cc*16, As + (size_t)row*DIM + k0 + cc*16);
            }
            #pragma unroll
            for (int it = 0; it < 4; it++){
                int c = it*256 + tid, row = c>>2, cc = c&3;
                CP16(st + 10240 + row*80 + cc*16, Bs + (size_t)row*DIM + k0 + cc*16);
            }
        } else {
            const int k0 = (kt - 32)*32;
            #pragma unroll
            for (int it = 0; it < 2; it++){
                int c = it*256 + tid, row = c>>2, cc = c&3;
                CP16(st + row*80 + cc*16, Ah + (size_t)row*DIM + k0 + cc*8);
            }
            #pragma unroll
            for (int it = 0; it < 4; it++){
                int c = it*256 + tid, row = c>>2, cc = c&3;
                CP16(st + 10240 + row*80 + cc*16, Bh + (size_t)row*DIM + k0 + cc*8);
            }
        }
        CP_COMMIT();
    };

    const int w = tid>>5, l = tid&31;
    const int wm = w>>2, wn = w&3;
    const int aoff = wm*64, boff = wn*64;
    const uint32_t apart = (uint32_t)((aoff + ((l>>3)&1)*8 + (l&7))*80 + (l>>4)*16);
    const uint32_t bpart = (uint32_t)((boff + (l>>4)*8 + (l&7))*80 + ((l>>3)&1)*16);

    // one accumulator array for both phases (int bits, then float bits)
    uint32_t accu[4][8][4];
    #pragma unroll
    for (int i=0;i<4;i++)
        #pragma unroll
        for (int j=0;j<8;j++)
            #pragma unroll
            for (int q=0;q<4;q++) accu[i][j][q] = 0u;

    issue(0); issue(1);
    // ---- int8 correction phase ----
    for (int kt = 0; kt < 32; kt++){
        CP_WAIT1();
        __syncthreads();
        issue(kt + 2);
        const uint32_t st = sb + (uint32_t)(kt%3)*30720u;
        #pragma unroll
        for (int ks = 0; ks < 2; ks++){
            uint32_t a[4][4], b[8][2];
            #pragma unroll
            for (int i=0;i<4;i++){
                uint32_t ad = st + apart + i*1280 + ks*32;
                LDSM4(a[i][0],a[i][1],a[i][2],a[i][3], ad);
            }
            #pragma unroll
            for (int jp=0;jp<4;jp++){
                uint32_t bd = st + 10240 + bpart + jp*1280 + ks*32;
                LDSM4(b[2*jp][0],b[2*jp][1],b[2*jp+1][0],b[2*jp+1][1], bd);
            }
            #pragma unroll
            for (int i=0;i<4;i++)
                #pragma unroll
                for (int j=0;j<8;j++) MMAI(((int*)accu[i][j]), a[i], b[j]);
        }
    }
    // in-place convert s32 -> f32*2^-22
    #pragma unroll
    for (int i=0;i<4;i++)
        #pragma unroll
        for (int j=0;j<8;j++)
            #pragma unroll
            for (int q=0;q<4;q++)
                accu[i][j][q] = __float_as_uint((float)(int)accu[i][j][q] * SINV);
    // ---- bf16 main phase (accumulates in place) ----
    for (int kt = 32; kt < 64; kt++){
        if (kt == 63) CP_WAIT0(); else CP_WAIT1();
        __syncthreads();
        if (kt + 2 < 64) issue(kt + 2);
        const uint32_t st = sb + (uint32_t)(kt%3)*30720u;
        #pragma unroll
        for (int ks = 0; ks < 2; ks++){
            uint32_t a[4][4], b[8][2];
            #pragma unroll
            for (int i=0;i<4;i++){
                uint32_t ad = st + apart + i*1280 + ks*32;
                LDSM4(a[i][0],a[i][1],a[i][2],a[i][3], ad);
            }
            #pragma unroll
            for (int jp=0;jp<4;jp++){
                uint32_t bd = st + 10240 + bpart + jp*1280 + ks*32;
                LDSM4(b[2*jp][0],b[2*jp][1],b[2*jp+1][0],b[2*jp+1][1], bd);
            }
            #pragma unroll
            for (int i=0;i<4;i++)
                #pragma unroll
                for (int j=0;j<8;j++) MMA(((float*)accu[i][j]), a[i], b[j]);
        }
    }

    // ---- fused epilogue ----
    const int mb = m0 + aoff, nb = n0 + boff;
    const int r0 = l>>2, c0 = (l&3)*2;
    const size_t base = (size_t)k*MD;
    #define ACCF(i,j,q) (*reinterpret_cast<float*>(&accu[i][j][q]))
    if (MODE == 0){
        const float* mu = (k==0) ? g_x : g_states + (size_t)(k-1)*MD;
        const float* bias = bst + k*DIM;
        __nv_bfloat16* eh = g_eh + base;
        int8_t *e1 = g_e1 + base, *e2 = g_e2 + base;
        #pragma unroll
        for (int i=0;i<4;i++)
            #pragma unroll
            for (int j=0;j<8;j++){
                const int n = nb + j*8 + c0;
                float2 bv = *reinterpret_cast<const float2*>(&bias[n]);
                #pragma unroll
                for (int h=0;h<2;h++){
                    const int m = mb + i*16 + r0 + h*8;
                    float2 mv = *reinterpret_cast<const float2*>(&mu[(size_t)m*DIM + n]);
                    float ex = mv.x - ACCF(i,j,h*2)   - bv.x;
                    float ey = mv.y - ACCF(i,j,h*2+1) - bv.y;
                    __nv_bfloat16 hx = __float2bfloat16(ex), hy = __float2bfloat16(ey);
                    __nv_bfloat162 hp; hp.x = hx; hp.y = hy;
                    *reinterpret_cast<__nv_bfloat162*>(&eh[(size_t)m*DIM + n]) = hp;
                    uint16_t p1 = (uint16_t)((q8(ex*16.f)&0xFF) | ((q8(ey*16.f)&0xFF)<<8));
                    uint16_t p2 = (uint16_t)((q8((ex-__bfloat162float(hx))*8192.f)&0xFF) |
                                             ((q8((ey-__bfloat162float(hy))*8192.f)&0xFF)<<8));
                    *reinterpret_cast<uint16_t*>(&e1[(size_t)m*DIM + n]) = p1;
                    *reinterpret_cast<uint16_t*>(&e2[(size_t)m*DIM + n]) = p2;
                }
            }
    } else {
        float* so = g_states + base;
        __nv_bfloat16* sh = g_sh + base;
        int8_t *s1 = g_s1 + base, *s2 = g_s2 + base;
        const __nv_bfloat16* enh = g_eh + (size_t)(k+1)*MD;
        const int8_t* ene2 = g_e2 + (size_t)(k+1)*MD;
        const bool he = (k < L_-1);
        #pragma unroll
        for (int i=0;i<4;i++)
            #pragma unroll
            for (int j=0;j<8;j++){
                const int n = nb + j*8 + c0;
                #pragma unroll
                for (int h=0;h<2;h++){
                    const int m = mb + i*16 + r0 + h*8;
                    float2 sv = *reinterpret_cast<const float2*>(&so[(size_t)m*DIM + n]);
                    float evx = 0.f, evy = 0.f;
                    if (he){
                        __nv_bfloat162 e1v = *reinterpret_cast<const __nv_bfloat162*>(&enh[(size_t)m*DIM + n]);
                        uint16_t e2v = *reinterpret_cast<const uint16_t*>(&ene2[(size_t)m*DIM + n]);
                        evx = __bfloat162float(e1v.x) + (float)((int8_t)(e2v & 0xFF)) * (1.f/8192.f);
                        evy = __bfloat162float(e1v.y) + (float)((int8_t)(e2v >> 8))   * (1.f/8192.f);
                    }
                    float nx = sv.x + LR*ACCF(i,j,h*2)   - LR*evx;
                    float ny = sv.y + LR*ACCF(i,j,h*2+1) - LR*evy;
                    float2 ov; ov.x = nx; ov.y = ny;
                    *reinterpret_cast<float2*>(&so[(size_t)m*DIM + n]) = ov;
                    __nv_bfloat16 hx = __float2bfloat16(nx), hy = __float2bfloat16(ny);
                    __nv_bfloat162 hp; hp.x = hx; hp.y = hy;
                    *reinterpret_cast<__nv_bfloat162*>(&sh[(size_t)m*DIM + n]) = hp;
                    uint16_t p1 = (uint16_t)((q8(nx*16.f)&0xFF) | ((q8(ny*16.f)&0xFF)<<8));
                    uint16_t p2 = (uint16_t)((q8((nx-__bfloat162float(hx))*8192.f)&0xFF) |
                                             ((q8((ny-__bfloat162float(hy))*8192.f)&0xFF)<<8));
                    *reinterpret_cast<uint16_t*>(&s1[(size_t)m*DIM + n]) = p1;
                    *reinterpret_cast<uint16_t*>(&s2[(size_t)m*DIM + n]) = p2;
                }
            }
    }
    #undef ACCF
}

// ---- CE: 128x128 bf16-hi logits tile + online softmax partials ----
__global__ __launch_bounds__(256,1)
void mm_ce(const int* __restrict__ targets, const float* __restrict__ oB){
    extern __shared__ char smem[];
    const uint32_t sb = smem_u32(smem);
    float* ls   = reinterpret_cast<float*>(smem + 61440);
    float* s_ob = reinterpret_cast<float*>(smem + 127488);
    int* s_ro   = reinterpret_cast<int*>(smem + 128000);
    int* s_tg   = reinterpret_cast<int*>(smem + 128512);
    const int tid = threadIdx.x;
    const int split = blockIdx.x, m0 = blockIdx.y*128, n0 = split*128;

    if (tid < 128){
        int rg = m0 + tid;
        if (rg < NROWS){
            int b = rg/(S_-1), s = rg%(S_-1);
            s_ro[tid] = (b*S_ + s)*DIM;
            s_tg[tid] = targets[b*S_ + s + 1];
        } else { s_ro[tid] = 0; s_tg[tid] = -1; }
        s_ob[tid] = oB[n0 + tid];
    }
    __syncthreads();

    const __nv_bfloat16* A3 = g_sh + (size_t)3*MD;
    const __nv_bfloat16* Bw = g_oWh + (size_t)n0*DIM;

    auto issue = [&](int kt){
        const uint32_t st = sb + (uint32_t)(kt%3)*20480u;
        const int k0 = kt*32;
        #pragma unroll
        for (int it = 0; it < 2; it++){
            int c = it*256 + tid, row = c>>2, cc = c&3;
            CP16(st + row*80 + cc*16, A3 + s_ro[row] + k0 + cc*8);
            CP16(st + 10240 + row*80 + cc*16, Bw + (size_t)row*DIM + k0 + cc*8);
        }
        CP_COMMIT();
    };

    const int w = tid>>5, l = tid&31;
    const int wm = w>>2, wn = w&3;
    const int aoff = wm*64, boff = wn*32;
    const uint32_t apart = (uint32_t)((aoff + ((l>>3)&1)*8 + (l&7))*80 + (l>>4)*16);
    const uint32_t bpart = (uint32_t)((boff + (l>>4)*8 + (l&7))*80 + ((l>>3)&1)*16);

    float acc[4][4][4];
    #pragma unroll
    for (int i=0;i<4;i++)
        #pragma unroll
        for (int j=0;j<4;j++)
            #pragma unroll
            for (int q=0;q<4;q++) acc[i][j][q] = 0.f;

    issue(0); issue(1);
    for (int kt = 0; kt < 32; kt++){
        if (kt == 31) CP_WAIT0(); else CP_WAIT1();
        __syncthreads();
        if (kt + 2 < 32) issue(kt + 2);
        const uint32_t st = sb + (uint32_t)(kt%3)*20480u;
        #pragma unroll
        for (int ks = 0; ks < 2; ks++){
            uint32_t ah[4][4], bh[4][2];
            #pragma unroll
            for (int i=0;i<4;i++){
                uint32_t ad = st + apart + i*1280 + ks*32;
                LDSM4(ah[i][0],ah[i][1],ah[i][2],ah[i][3], ad);
            }
            #pragma unroll
            for (int jp=0;jp<2;jp++){
                uint32_t bd = st + 10240 + bpart + jp*1280 + ks*32;
                LDSM4(bh[2*jp][0],bh[2*jp][1],bh[2*jp+1][0],bh[2*jp+1][1], bd);
            }
            #pragma unroll
            for (int i=0;i<4;i++)
                #pragma unroll
                for (int j=0;j<4;j++)
                    MMA(acc[i][j], ah[i], bh[j]);
        }
    }

    const int r0 = l>>2, c0 = (l&3)*2;
    #pragma unroll
    for (int i=0;i<4;i++)
        #pragma unroll
        for (int j=0;j<4;j++)
            #pragma unroll
            for (int h=0;h<2;h++){
                int rr = aoff + i*16 + r0 + h*8;
                int cc = boff + j*8 + c0;
                ls[rr*129 + cc]     = acc[i][j][h*2];
                ls[rr*129 + cc + 1] = acc[i][j][h*2+1];
            }
    __syncthreads();

    if (tid < 128){
        const int r = m0 + tid, tg = s_tg[tid];
        float mx = -1e30f;
        #pragma unroll 8
        for (int c = 0; c < 128; c++){
            float v = ls[tid*129 + c] + s_ob[c];
            mx = fmaxf(mx, v);
        }
        float sm = 0.f, tl = -1e30f;
        #pragma unroll 8
        for (int c = 0; c < 128; c++){
            float v = ls[tid*129 + c] + s_ob[c];
            sm += __expf(v - mx);
            if (n0 + c == tg) tl = v;
        }
        if (r < NROWS){
            g_pm[r*NSP + split] = mx;
            g_ps[r*NSP + split] = sm;
            g_pt[r*NSP + split] = tl;
        }
    }
}

// ---- reductions ----
__global__ void pc_reduce_kernel(){
    __shared__ double sm[256];
    double local = 0.0;
    const uint4* H = reinterpret_cast<const uint4*>(g_eh);
    const uint2* E2 = reinterpret_cast<const uint2*>(g_e2);
    for (int i = blockIdx.x*blockDim.x + threadIdx.x; i < LMD/8; i += gridDim.x*blockDim.x){
        uint4 hv = H[i]; uint2 e2v = E2[i];
        const __nv_bfloat162* hp = reinterpret_cast<const __nv_bfloat162*>(&hv);
        const int8_t* lb = reinterpret_cast<const int8_t*>(&e2v);
        #pragma unroll
        for (int q = 0; q < 4; q++){
            float ex = __bfloat162float(hp[q].x) + (float)lb[q*2]   * (1.f/8192.f);
            float ey = __bfloat162float(hp[q].y) + (float)lb[q*2+1] * (1.f/8192.f);
            local += (double)ex*ex + (double)ey*ey;
        }
    }
    sm[threadIdx.x] = local; __syncthreads();
    for (int s = 128; s > 0; s >>= 1){
        if (threadIdx.x < s) sm[threadIdx.x] += sm[threadIdx.x + s];
        __syncthreads();
    }
    if (threadIdx.x == 0) g_pc_part[blockIdx.x] = sm[0];
}
__global__ void ce_combine_kernel(){
    __shared__ double sm[256];
    double local = 0.0;
    for (int r = blockIdx.x*blockDim.x + threadIdx.x; r < NROWS; r += gridDim.x*blockDim.x){
        float M = -1e30f;
        for (int sp = 0; sp < NSP; sp++) M = fmaxf(M, g_pm[r*NSP + sp]);
        float Z = 0.f;
        for (int sp = 0; sp < NSP; sp++) Z += g_ps[r*NSP + sp]*__expf(g_pm[r*NSP + sp] - M);
        float tl = -1e30f;
        for (int sp = 0; sp < NSP; sp++) tl = fmaxf(tl, g_pt[r*NSP + sp]);
        local += (double)M + log((double)Z) - (double)tl;
    }
    sm[threadIdx.x] = local; __syncthreads();
    for (int s = 128; s > 0; s >>= 1){
        if (threadIdx.x < s) sm[threadIdx.x] += sm[threadIdx.x + s];
        __syncthreads();
    }
    if (threadIdx.x == 0) g_ce_part[blockIdx.x] = sm[0];
}
__global__ void finalize_kernel(float* out){
    double pc = 0.0, ce = 0.0;
    for (int i = 0; i < NPCB; i++) pc += g_pc_part[i];
    for (int i = 0; i < NCEB; i++) ce += g_ce_part[i];
    out[0] = (float)(ce/(double)NROWS);
    out[1] = (float)(pc/(double)LMD);
}

// ---- launch ----
extern "C" void kernel_launch(void* const* d_in, const int* in_sizes, int n_in,
                              void* d_out, int out_size){
    const int*   input_ids   = (const int*)d_in[0];
    const int*   targets     = (const int*)d_in[1];
    const float* emb         = (const float*)d_in[2];
    const float* W_stack     = (const float*)d_in[3];
    const float* b_stack     = (const float*)d_in[4];
    const float* out_W       = (const float*)d_in[5];
    const float* out_b       = (const float*)d_in[6];
    const float* states_init = (const float*)d_in[7];
    float* out = (float*)d_out;

    constexpr int GSMEM = 3*30720;     // 90 KB
    constexpr int CSMEM = 129024;      // ~126 KB
    cudaFuncSetAttribute(mm_step<0>, cudaFuncAttributeMaxDynamicSharedMemorySize, GSMEM);
    cudaFuncSetAttribute(mm_step<1>, cudaFuncAttributeMaxDynamicSharedMemorySize, GSMEM);
    cudaFuncSetAttribute(mm_ce,      cudaFuncAttributeMaxDynamicSharedMemorySize, CSMEM);

    split_states_kernel<<<LMD/1024, 256>>>(states_init);
    gather_kernel<<<M_, 256>>>(input_ids, emb);
    split_w_kernel<<<dim3(32,32,L_), dim3(32,8)>>>(W_stack);
    split_ow_kernel<<<(V_*DIM)/1024, 256>>>(out_W);

    dim3 gg(DIM/256, M_/128, L_);   // (4, 32, 4) = 512 blocks, layers fused
    for (int step = 0; step < STEPS; step++){
        mm_step<0><<<gg, 256, GSMEM>>>(b_stack);
        mm_step<1><<<gg, 256, GSMEM>>>(b_stack);
    }
    mm_step<0><<<gg, 256, GSMEM>>>(b_stack);

    pc_reduce_kernel<<<NPCB, 256>>>();
    mm_ce<<<dim3(NSP, M_/128), 256, CSMEM>>>(targets, out_b);
    ce_combine_kernel<<<NCEB, 256>>>();
    finalize_kernel<<<1, 1>>>(out);
}

// round 15
// speedup vs baseline: 1.6184x; 1.6184x over previous
#include <cuda_runtime.h>
#include <cuda_fp16.h>
#include <math.h>
#include <stdint.h>

#define DIM 1024
constexpr int B_ = 8, S_ = 512, L_ = 4;
constexpr int M_ = B_ * S_;
constexpr int V_ = 32000;
constexpr int STEPS = 8;
constexpr float LR = 0.1f;
constexpr int MD = M_ * DIM, LMD = L_ * MD;
constexpr int NROWS = B_ * (S_ - 1);
constexpr int NSP = V_ / 128;     // 250
constexpr int NPCB = 256, NCEB = 16;
constexpr float SC   = 16384.f;        // 2^14
constexpr float SCINV = 1.f/16384.f;   // 2^-14

__device__ float g_x[MD];
__device__ float g_states[LMD];
__device__ __half g_sh[LMD], g_eh[LMD];          // fp16 hi
__device__ uint8_t g_s1[LMD], g_s2[LMD], g_e1[LMD], g_e2[LMD]; // fp8(val), fp8(res*2^14)
__device__ __half g_Wh[L_*DIM*DIM], g_Wth[L_*DIM*DIM];
__device__ uint8_t g_Wl8[L_*DIM*DIM], g_Wh8[L_*DIM*DIM];
__device__ uint8_t g_Wtl8[L_*DIM*DIM], g_Wth8[L_*DIM*DIM];
__device__ __half g_oWh[V_*DIM];
__device__ float g_pm[4096*NSP], g_ps[4096*NSP], g_pt[4096*NSP];
__device__ double g_pc_part[NPCB], g_ce_part[NCEB];

// ---- helpers ----
__device__ __forceinline__ uint32_t smem_u32(const void* p){
    uint32_t a; asm("{ .reg .u64 t; cvta.to.shared.u64 t, %1; cvt.u32.u64 %0, t; }":"=r"(a):"l"(p)); return a;
}
// pack two floats -> e4m3x2 (v0 -> low byte = lower address)
__device__ __forceinline__ uint16_t fp8pair(float v0, float v1){
    uint16_t r;
    asm("cvt.rn.satfinite.e4m3x2.f32 %0, %1, %2;" : "=h"(r) : "f"(v1), "f"(v0));
    return r;
}
// e4m3x2 -> float2 (low byte -> .x)
__device__ __forceinline__ float2 fp8unpair(uint16_t p){
    uint32_t h2;
    asm("cvt.rn.f16x2.e4m3x2 %0, %1;" : "=r"(h2) : "h"(p));
    __half2 hh = *reinterpret_cast<__half2*>(&h2);
    return __half22float2(hh);
}
#define CP16(dst, src) \
    asm volatile("cp.async.cg.shared.global [%0], [%1], 16;" \
        :: "r"(dst), "l"(__cvta_generic_to_global(src)) : "memory")
#define CP_COMMIT() asm volatile("cp.async.commit_group;" ::: "memory")
#define CP_WAIT1()  asm volatile("cp.async.wait_group 1;" ::: "memory")
#define CP_WAIT0()  asm volatile("cp.async.wait_group 0;" ::: "memory")
#define LDSM4(r0,r1,r2,r3,addr) \
    asm volatile("ldmatrix.sync.aligned.m8n8.x4.shared.b16 {%0,%1,%2,%3}, [%4];" \
        : "=r"(r0),"=r"(r1),"=r"(r2),"=r"(r3) : "r"(addr))
#define MMAH(d, a, b) \
    asm volatile("mma.sync.aligned.m16n8k16.row.col.f32.f16.f16.f32 " \
        "{%0,%1,%2,%3},{%4,%5,%6,%7},{%8,%9},{%0,%1,%2,%3};" \
        : "+f"((d)[0]),"+f"((d)[1]),"+f"((d)[2]),"+f"((d)[3]) \
        : "r"((a)[0]),"r"((a)[1]),"r"((a)[2]),"r"((a)[3]),"r"((b)[0]),"r"((b)[1]))
#define MMA8(d, a, b) \
    asm volatile("mma.sync.aligned.m16n8k32.row.col.f32.e4m3.e4m3.f32 " \
        "{%0,%1,%2,%3},{%4,%5,%6,%7},{%8,%9},{%0,%1,%2,%3};" \
        : "+f"((d)[0]),"+f"((d)[1]),"+f"((d)[2]),"+f"((d)[3]) \
        : "r"((a)[0]),"r"((a)[1]),"r"((a)[2]),"r"((a)[3]),"r"((b)[0]),"r"((b)[1]))

// ---- prep kernels ----
__global__ void gather_kernel(const int* __restrict__ ids, const float* __restrict__ emb){
    int row = blockIdx.x, id = ids[row];
    reinterpret_cast<float4*>(g_x + (size_t)row*DIM)[threadIdx.x] =
        reinterpret_cast<const float4*>(emb + (size_t)id*DIM)[threadIdx.x];
}
__global__ void split_states_kernel(const float* __restrict__ si){
    int i = blockIdx.x*blockDim.x + threadIdx.x;   // over LMD/4
    float4 v = reinterpret_cast<const float4*>(si)[i];
    reinterpret_cast<float4*>(g_states)[i] = v;
    float e[4] = {v.x, v.y, v.z, v.w};
    __half2 hp[2];
    hp[0] = __floats2half2_rn(e[0], e[1]);
    hp[1] = __floats2half2_rn(e[2], e[3]);
    uint32_t p1 = (uint32_t)fp8pair(e[0], e[1]) | ((uint32_t)fp8pair(e[2], e[3]) << 16);
    float r0 = (e[0] - __half2float(hp[0].x))*SC, r1 = (e[1] - __half2float(hp[0].y))*SC;
    float r2 = (e[2] - __half2float(hp[1].x))*SC, r3 = (e[3] - __half2float(hp[1].y))*SC;
    uint32_t p2 = (uint32_t)fp8pair(r0, r1) | ((uint32_t)fp8pair(r2, r3) << 16);
    reinterpret_cast<uint2*>(g_sh)[i] = *reinterpret_cast<uint2*>(hp);
    reinterpret_cast<uint32_t*>(g_s1)[i] = p1;
    reinterpret_cast<uint32_t*>(g_s2)[i] = p2;
}
__global__ void split_w_kernel(const float* __restrict__ W){
    __shared__ float tile[32][33];
    int l = blockIdx.z, i0 = blockIdx.y*32, j0 = blockIdx.x*32;
    int tx = threadIdx.x, ty = threadIdx.y;
    const float* Wb = W + (size_t)l*DIM*DIM;
    #pragma unroll
    for (int r = 0; r < 4; r++){
        int i = i0 + ty + r*8;
        float w = Wb[(size_t)i*DIM + j0 + tx];
        __half h = __float2half(w);
        float hf = __half2float(h);
        size_t o = (size_t)l*DIM*DIM + (size_t)i*DIM + j0 + tx;
        g_Wh[o] = h;
        uint16_t pr = fp8pair((w - hf)*SC, 0.f);
        g_Wl8[o] = (uint8_t)(pr & 0xFF);
        uint16_t ph = fp8pair(w, 0.f);
        g_Wh8[o] = (uint8_t)(ph & 0xFF);
        tile[ty + r*8][tx] = w;
    }
    __syncthreads();
    #pragma unroll
    for (int r = 0; r < 4; r++){
        int jr = ty + r*8;
        float w = tile[tx][jr];
        __half h = __float2half(w);
        float hf = __half2float(h);
        size_t o = (size_t)l*DIM*DIM + (size_t)(j0+jr)*DIM + i0 + tx;
        g_Wth[o] = h;
        uint16_t pr = fp8pair((w - hf)*SC, 0.f);
        g_Wtl8[o] = (uint8_t)(pr & 0xFF);
        uint16_t ph = fp8pair(w, 0.f);
        g_Wth8[o] = (uint8_t)(ph & 0xFF);
    }
}
__global__ void split_ow_kernel(const float* __restrict__ oW){
    int i = blockIdx.x*blockDim.x + threadIdx.x;   // over V*DIM/4
    float4 v = reinterpret_cast<const float4*>(oW)[i];
    __half2 hp[2];
    hp[0] = __floats2half2_rn(v.x, v.y);
    hp[1] = __floats2half2_rn(v.z, v.w);
    reinterpret_cast<uint2*>(g_oWh)[i] = *reinterpret_cast<uint2*>(hp);
}

// ---- step GEMM: 128x256 block, 8 warps of 64x64, unified 64-kt loop ----
// kts 0-15:  fp8  fp8(A)       x fp8(Wl*2^14)     (64 k-vals/kt)
// kts 16-31: fp8  fp8(Al*2^14) x fp8(W)           -> f32 acc, then acc *= 2^-14
// kts 32-63: fp16 Ah x Wh                          (32 k-vals/kt, adds on top)
// Single f32 accumulator throughout. stage 30720B: A@0 (128x64B, str 80), B@10240 (256x64B, str 80)
template<int MODE>
__global__ __launch_bounds__(256,1)
void mm_step(const float* __restrict__ bst){
    extern __shared__ char smem[];
    const uint32_t sb = smem_u32(smem);
    const int tid = threadIdx.x;
    const int k = blockIdx.z;
    const int m0 = blockIdx.y*128, n0 = blockIdx.x*256;
    const size_t abase = (size_t)k*MD + (size_t)m0*DIM;
    const size_t bbase = (size_t)k*DIM*DIM + (size_t)n0*DIM;
    const __half*   Ah  = (MODE==0?g_sh:g_eh) + abase;
    const uint8_t*  A1  = (MODE==0?g_s1:g_e1) + abase;
    const uint8_t*  A2  = (MODE==0?g_s2:g_e2) + abase;
    const __half*   Bh  = (MODE==0?g_Wh:g_Wth) + bbase;
    const uint8_t*  Bl8 = (MODE==0?g_Wl8:g_Wtl8) + bbase;
    const uint8_t*  Bh8 = (MODE==0?g_Wh8:g_Wth8) + bbase;

    auto issue = [&](int kt){
        const uint32_t st = sb + (uint32_t)(kt%3)*30720u;
        if (kt < 32){
            const uint8_t* As = (kt < 16) ? A1 : A2;
            const uint8_t* Bs = (kt < 16) ? Bl8 : Bh8;
            const int k0 = (kt & 15)*64;
            #pragma unroll
            for (int it = 0; it < 2; it++){
                int c = it*256 + tid, row = c>>2, cc = c&3;
                CP16(st + row*80 + cc*16, As + (size_t)row*DIM + k0 + cc*16);
            }
            #pragma unroll
            for (int it = 0; it < 4; it++){
                int c = it*256 + tid, row = c>>2, cc = c&3;
                CP16(st + 10240 + row*80 + cc*16, Bs + (size_t)row*DIM + k0 + cc*16);
            }
        } else {
            const int k0 = (kt - 32)*32;
            #pragma unroll
            for (int it = 0; it < 2; it++){
                int c = it*256 + tid, row = c>>2, cc = c&3;
                CP16(st + row*80 + cc*16, Ah + (size_t)row*DIM + k0 + cc*8);
            }
            #pragma unroll
            for (int it = 0; it < 4; it++){
                int c = it*256 + tid, row = c>>2, cc = c&3;
                CP16(st + 10240 + row*80 + cc*16, Bh + (size_t)row*DIM + k0 + cc*8);
            }
        }
        CP_COMMIT();
    };

    const int w = tid>>5, l = tid&31;
    const int wm = w>>2, wn = w&3;
    const int aoff = wm*64, boff = wn*64;
    const uint32_t apart = (uint32_t)((aoff + ((l>>3)&1)*8 + (l&7))*80 + (l>>4)*16);
    const uint32_t bpart = (uint32_t)((boff + (l>>4)*8 + (l&7))*80 + ((l>>3)&1)*16);

    float acc[4][8][4];
    #pragma unroll
    for (int i=0;i<4;i++)
        #pragma unroll
        for (int j=0;j<8;j++)
            #pragma unroll
            for (int q=0;q<4;q++) acc[i][j][q] = 0.f;

    issue(0); issue(1);
    // ---- fp8 correction phase ----
    for (int kt = 0; kt < 32; kt++){
        CP_WAIT1();
        __syncthreads();
        issue(kt + 2);
        const uint32_t st = sb + (uint32_t)(kt%3)*30720u;
        #pragma unroll
        for (int ks = 0; ks < 2; ks++){
            uint32_t a[4][4], b[8][2];
            #pragma unroll
            for (int i=0;i<4;i++){
                uint32_t ad = st + apart + i*1280 + ks*32;
                LDSM4(a[i][0],a[i][1],a[i][2],a[i][3], ad);
            }
            #pragma unroll
            for (int jp=0;jp<4;jp++){
                uint32_t bd = st + 10240 + bpart + jp*1280 + ks*32;
                LDSM4(b[2*jp][0],b[2*jp][1],b[2*jp+1][0],b[2*jp+1][1], bd);
            }
            #pragma unroll
            for (int i=0;i<4;i++)
                #pragma unroll
                for (int j=0;j<8;j++) MMA8(acc[i][j], a[i], b[j]);
        }
    }
    // rescale correction sum by 2^-14
    #pragma unroll
    for (int i=0;i<4;i++)
        #pragma unroll
        for (int j=0;j<8;j++)
            #pragma unroll
            for (int q=0;q<4;q++) acc[i][j][q] *= SCINV;
    // ---- fp16 main phase ----
    for (int kt = 32; kt < 64; kt++){
        if (kt == 63) CP_WAIT0(); else CP_WAIT1();
        __syncthreads();
        if (kt + 2 < 64) issue(kt + 2);
        const uint32_t st = sb + (uint32_t)(kt%3)*30720u;
        #pragma unroll
        for (int ks = 0; ks < 2; ks++){
            uint32_t a[4][4], b[8][2];
            #pragma unroll
            for (int i=0;i<4;i++){
                uint32_t ad = st + apart + i*1280 + ks*32;
                LDSM4(a[i][0],a[i][1],a[i][2],a[i][3], ad);
            }
            #pragma unroll
            for (int jp=0;jp<4;jp++){
                uint32_t bd = st + 10240 + bpart + jp*1280 + ks*32;
                LDSM4(b[2*jp][0],b[2*jp][1],b[2*jp+1][0],b[2*jp+1][1], bd);
            }
            #pragma unroll
            for (int i=0;i<4;i++)
                #pragma unroll
                for (int j=0;j<8;j++) MMAH(acc[i][j], a[i], b[j]);
        }
    }

    // ---- fused epilogue ----
    const int mb = m0 + aoff, nb = n0 + boff;
    const int r0 = l>>2, c0 = (l&3)*2;
    const size_t base = (size_t)k*MD;
    if (MODE == 0){
        const float* mu = (k==0) ? g_x : g_states + (size_t)(k-1)*MD;
        const float* bias = bst + k*DIM;
        __half* eh = g_eh + base;
        uint8_t *e1 = g_e1 + base, *e2 = g_e2 + base;
        #pragma unroll
        for (int i=0;i<4;i++)
            #pragma unroll
            for (int j=0;j<8;j++){
                const int n = nb + j*8 + c0;
                float2 bv = *reinterpret_cast<const float2*>(&bias[n]);
                #pragma unroll
                for (int h=0;h<2;h++){
                    const int m = mb + i*16 + r0 + h*8;
                    float2 mv = *reinterpret_cast<const float2*>(&mu[(size_t)m*DIM + n]);
                    float ex = mv.x - acc[i][j][h*2]   - bv.x;
                    float ey = mv.y - acc[i][j][h*2+1] - bv.y;
                    __half2 hp = __floats2half2_rn(ex, ey);
                    *reinterpret_cast<__half2*>(&eh[(size_t)m*DIM + n]) = hp;
                    *reinterpret_cast<uint16_t*>(&e1[(size_t)m*DIM + n]) = fp8pair(ex, ey);
                    float rx = (ex - __half2float(hp.x))*SC;
                    float ry = (ey - __half2float(hp.y))*SC;
                    *reinterpret_cast<uint16_t*>(&e2[(size_t)m*DIM + n]) = fp8pair(rx, ry);
                }
            }
    } else {
        float* so = g_states + base;
        __half* sh = g_sh + base;
        uint8_t *s1 = g_s1 + base, *s2 = g_s2 + base;
        const __half* enh = g_eh + (size_t)(k+1)*MD;
        const uint8_t* ene2 = g_e2 + (size_t)(k+1)*MD;
        const bool he = (k < L_-1);
        #pragma unroll
        for (int i=0;i<4;i++)
            #pragma unroll
            for (int j=0;j<8;j++){
                const int n = nb + j*8 + c0;
                #pragma unroll
                for (int h=0;h<2;h++){
                    const int m = mb + i*16 + r0 + h*8;
                    float2 sv = *reinterpret_cast<const float2*>(&so[(size_t)m*DIM + n]);
                    float evx = 0.f, evy = 0.f;
                    if (he){
                        __half2 e1v = *reinterpret_cast<const __half2*>(&enh[(size_t)m*DIM + n]);
                        uint16_t e2v = *reinterpret_cast<const uint16_t*>(&ene2[(size_t)m*DIM + n]);
                        float2 lo = fp8unpair(e2v);
                        evx = __half2float(e1v.x) + lo.x*SCINV;
                        evy = __half2float(e1v.y) + lo.y*SCINV;
                    }
                    float nx = sv.x + LR*acc[i][j][h*2]   - LR*evx;
                    float ny = sv.y + LR*acc[i][j][h*2+1] - LR*evy;
                    float2 ov; ov.x = nx; ov.y = ny;
                    *reinterpret_cast<float2*>(&so[(size_t)m*DIM + n]) = ov;
                    __half2 hp = __floats2half2_rn(nx, ny);
                    *reinterpret_cast<__half2*>(&sh[(size_t)m*DIM + n]) = hp;
                    *reinterpret_cast<uint16_t*>(&s1[(size_t)m*DIM + n]) = fp8pair(nx, ny);
                    float rx = (nx - __half2float(hp.x))*SC;
                    float ry = (ny - __half2float(hp.y))*SC;
                    *reinterpret_cast<uint16_t*>(&s2[(size_t)m*DIM + n]) = fp8pair(rx, ry);
                }
            }
    }
}

// ---- CE: 128x128 fp16 logits tile + online softmax partials ----
__global__ __launch_bounds__(256,1)
void mm_ce(const int* __restrict__ targets, const float* __restrict__ oB){
    extern __shared__ char smem[];
    const uint32_t sb = smem_u32(smem);
    float* ls   = reinterpret_cast<float*>(smem + 61440);
    float* s_ob = reinterpret_cast<float*>(smem + 127488);
    int* s_ro   = reinterpret_cast<int*>(smem + 128000);
    int* s_tg   = reinterpret_cast<int*>(smem + 128512);
    const int tid = threadIdx.x;
    const int split = blockIdx.x, m0 = blockIdx.y*128, n0 = split*128;

    if (tid < 128){
        int rg = m0 + tid;
        if (rg < NROWS){
            int b = rg/(S_-1), s = rg%(S_-1);
            s_ro[tid] = (b*S_ + s)*DIM;
            s_tg[tid] = targets[b*S_ + s + 1];
        } else { s_ro[tid] = 0; s_tg[tid] = -1; }
        s_ob[tid] = oB[n0 + tid];
    }
    __syncthreads();

    const __half* A3 = g_sh + (size_t)3*MD;
    const __half* Bw = g_oWh + (size_t)n0*DIM;

    auto issue = [&](int kt){
        const uint32_t st = sb + (uint32_t)(kt%3)*20480u;
        const int k0 = kt*32;
        #pragma unroll
        for (int it = 0; it < 2; it++){
            int c = it*256 + tid, row = c>>2, cc = c&3;
            CP16(st + row*80 + cc*16, A3 + s_ro[row] + k0 + cc*8);
            CP16(st + 10240 + row*80 + cc*16, Bw + (size_t)row*DIM + k0 + cc*8);
        }
        CP_COMMIT();
    };

    const int w = tid>>5, l = tid&31;
    const int wm = w>>2, wn = w&3;
    const int aoff = wm*64, boff = wn*32;
    const uint32_t apart = (uint32_t)((aoff + ((l>>3)&1)*8 + (l&7))*80 + (l>>4)*16);
    const uint32_t bpart = (uint32_t)((boff + (l>>4)*8 + (l&7))*80 + ((l>>3)&1)*16);

    float acc[4][4][4];
    #pragma unroll
    for (int i=0;i<4;i++)
        #pragma unroll
        for (int j=0;j<4;j++)
            #pragma unroll
            for (int q=0;q<4;q++) acc[i][j][q] = 0.f;

    issue(0); issue(1);
    for (int kt = 0; kt < 32; kt++){
        if (kt == 31) CP_WAIT0(); else CP_WAIT1();
        __syncthreads();
        if (kt + 2 < 32) issue(kt + 2);
        const uint32_t st = sb + (uint32_t)(kt%3)*20480u;
        #pragma unroll
        for (int ks = 0; ks < 2; ks++){
            uint32_t ah[4][4], bh[4][2];
            #pragma unroll
            for (int i=0;i<4;i++){
                uint32_t ad = st + apart + i*1280 + ks*32;
                LDSM4(ah[i][0],ah[i][1],ah[i][2],ah[i][3], ad);
            }
            #pragma unroll
            for (int jp=0;jp<2;jp++){
                uint32_t bd = st + 10240 + bpart + jp*1280 + ks*32;
                LDSM4(bh[2*jp][0],bh[2*jp][1],bh[2*jp+1][0],bh[2*jp+1][1], bd);
            }
            #pragma unroll
            for (int i=0;i<4;i++)
                #pragma unroll
                for (int j=0;j<4;j++)
                    MMAH(acc[i][j], ah[i], bh[j]);
        }
    }

    const int r0 = l>>2, c0 = (l&3)*2;
    #pragma unroll
    for (int i=0;i<4;i++)
        #pragma unroll
        for (int j=0;j<4;j++)
            #pragma unroll
            for (int h=0;h<2;h++){
                int rr = aoff + i*16 + r0 + h*8;
                int cc = boff + j*8 + c0;
                ls[rr*129 + cc]     = acc[i][j][h*2];
                ls[rr*129 + cc + 1] = acc[i][j][h*2+1];
            }
    __syncthreads();

    if (tid < 128){
        const int r = m0 + tid, tg = s_tg[tid];
        float mx = -1e30f;
        #pragma unroll 8
        for (int c = 0; c < 128; c++){
            float v = ls[tid*129 + c] + s_ob[c];
            mx = fmaxf(mx, v);
        }
        float sm = 0.f, tl = -1e30f;
        #pragma unroll 8
        for (int c = 0; c < 128; c++){
            float v = ls[tid*129 + c] + s_ob[c];
            sm += __expf(v - mx);
            if (n0 + c == tg) tl = v;
        }
        if (r < NROWS){
            g_pm[r*NSP + split] = mx;
            g_ps[r*NSP + split] = sm;
            g_pt[r*NSP + split] = tl;
        }
    }
}

// ---- reductions ----
__global__ void pc_reduce_kernel(){
    __shared__ double sm[256];
    double local = 0.0;
    const uint4* H = reinterpret_cast<const uint4*>(g_eh);
    const uint2* E2 = reinterpret_cast<const uint2*>(g_e2);
    for (int i = blockIdx.x*blockDim.x + threadIdx.x; i < LMD/8; i += gridDim.x*blockDim.x){
        uint4 hv = H[i]; uint2 e2v = E2[i];
        const __half2* hp = reinterpret_cast<const __half2*>(&hv);
        const uint16_t* lp = reinterpret_cast<const uint16_t*>(&e2v);
        #pragma unroll
        for (int q = 0; q < 4; q++){
            float2 lo = fp8unpair(lp[q]);
            float ex = __half2float(hp[q].x) + lo.x*SCINV;
            float ey = __half2float(hp[q].y) + lo.y*SCINV;
            local += (double)ex*ex + (double)ey*ey;
        }
    }
    sm[threadIdx.x] = local; __syncthreads();
    for (int s = 128; s > 0; s >>= 1){
        if (threadIdx.x < s) sm[threadIdx.x] += sm[threadIdx.x + s];
        __syncthreads();
    }
    if (threadIdx.x == 0) g_pc_part[blockIdx.x] = sm[0];
}
__global__ void ce_combine_kernel(){
    __shared__ double sm[256];
    double local = 0.0;
    for (int r = blockIdx.x*blockDim.x + threadIdx.x; r < NROWS; r += gridDim.x*blockDim.x){
        float M = -1e30f;
        for (int sp = 0; sp < NSP; sp++) M = fmaxf(M, g_pm[r*NSP + sp]);
        float Z = 0.f;
        for (int sp = 0; sp < NSP; sp++) Z += g_ps[r*NSP + sp]*__expf(g_pm[r*NSP + sp] - M);
        float tl = -1e30f;
        for (int sp = 0; sp < NSP; sp++) tl = fmaxf(tl, g_pt[r*NSP + sp]);
        local += (double)M + log((double)Z) - (double)tl;
    }
    sm[threadIdx.x] = local; __syncthreads();
    for (int s = 128; s > 0; s >>= 1){
        if (threadIdx.x < s) sm[threadIdx.x] += sm[threadIdx.x + s];
        __syncthreads();
    }
    if (threadIdx.x == 0) g_ce_part[blockIdx.x] = sm[0];
}
__global__ void finalize_kernel(float* out){
    double pc = 0.0, ce = 0.0;
    for (int i = 0; i < NPCB; i++) pc += g_pc_part[i];
    for (int i = 0; i < NCEB; i++) ce += g_ce_part[i];
    out[0] = (float)(ce/(double)NROWS);
    out[1] = (float)(pc/(double)LMD);
}

// ---- launch ----
extern "C" void kernel_launch(void* const* d_in, const int* in_sizes, int n_in,
                              void* d_out, int out_size){
    const int*   input_ids   = (const int*)d_in[0];
    const int*   targets     = (const int*)d_in[1];
    const float* emb         = (const float*)d_in[2];
    const float* W_stack     = (const float*)d_in[3];
    const float* b_stack     = (const float*)d_in[4];
    const float* out_W       = (const float*)d_in[5];
    const float* out_b       = (const float*)d_in[6];
    const float* states_init = (const float*)d_in[7];
    float* out = (float*)d_out;

    constexpr int GSMEM = 3*30720;     // 90 KB
    constexpr int CSMEM = 129024;      // ~126 KB
    cudaFuncSetAttribute(mm_step<0>, cudaFuncAttributeMaxDynamicSharedMemorySize, GSMEM);
    cudaFuncSetAttribute(mm_step<1>, cudaFuncAttributeMaxDynamicSharedMemorySize, GSMEM);
    cudaFuncSetAttribute(mm_ce,      cudaFuncAttributeMaxDynamicSharedMemorySize, CSMEM);

    split_states_kernel<<<LMD/1024, 256>>>(states_init);
    gather_kernel<<<M_, 256>>>(input_ids, emb);
    split_w_kernel<<<dim3(32,32,L_), dim3(32,8)>>>(W_stack);
    split_ow_kernel<<<(V_*DIM)/1024, 256>>>(out_W);

    dim3 gg(DIM/256, M_/128, L_);   // (4, 32, 4) = 512 blocks, layers fused
    for (int step = 0; step < STEPS; step++){
        mm_step<0><<<gg, 256, GSMEM>>>(b_stack);
        mm_step<1><<<gg, 256, GSMEM>>>(b_stack);
    }
    mm_step<0><<<gg, 256, GSMEM>>>(b_stack);

    pc_reduce_kernel<<<NPCB, 256>>>();
    mm_ce<<<dim3(NSP, M_/128), 256, CSMEM>>>(targets, out_b);
    ce_combine_kernel<<<NCEB, 256>>>();
    finalize_kernel<<<1, 1>>>(out);
}